// round 14
// baseline (speedup 1.0000x reference)
#include <cuda_runtime.h>
#include <cuda_fp16.h>
#include <cstdint>

#define BB 4
#define CC 256
#define HH 56
#define WW 56
#define CO 128
#define NT 49
#define HW 3136
#define GTOT 392          // 49 taps x 8 ci-blocks of 32
#define KSPL 3
#define XPR 68            // padded image 68x68
#define XPCH (XPR * XPR)  // 4624
#define NPC (BB * CC * XPCH)

typedef unsigned long long u64;

// ---- device-global scratch ----
__device__ __align__(16) __half g_W1bh[GTOT * 4096];        // half weights [g][co][k]
__device__ __align__(16) float  g_xpadf[NPC];               // padded x float (gather)
__device__ __align__(16) __half g_xh[2 * NPC];              // padded x half, 2 parities
__device__ __align__(16) float  g_part[KSPL * BB * CO * HW];// conv1 K-split partials
__device__ __align__(16) float  g_attn[BB * NT * HW];       // softmax attention

// ---------- helpers ----------
__device__ __forceinline__ uint32_t smem_to_u32(const void* p) {
    uint32_t a;
    asm("{ .reg .u64 t; cvta.to.shared.u64 t, %1; cvt.u32.u64 %0, t; }" : "=r"(a) : "l"(p));
    return a;
}
#define CP16(dst, src) \
    asm volatile("cp.async.cg.shared.global [%0], [%1], 16;" :: "r"(dst), "l"(src) : "memory")
#define CP8(dst, src) \
    asm volatile("cp.async.ca.shared.global [%0], [%1], 8;" :: "r"(dst), "l"(src) : "memory")
#define CP_COMMIT() asm volatile("cp.async.commit_group;" ::: "memory")
#define CP_WAIT0()  asm volatile("cp.async.wait_group 0;" ::: "memory")
#define CP_WAIT2()  asm volatile("cp.async.wait_group 2;" ::: "memory")

#define LDMX4T(r, addr) \
    asm volatile("ldmatrix.sync.aligned.m8n8.x4.trans.shared.b16 {%0,%1,%2,%3}, [%4];" \
        : "=r"((r)[0]), "=r"((r)[1]), "=r"((r)[2]), "=r"((r)[3]) : "r"(addr))
#define LDMX2(r, addr) \
    asm volatile("ldmatrix.sync.aligned.m8n8.x2.shared.b16 {%0,%1}, [%2];" \
        : "=r"((r)[0]), "=r"((r)[1]) : "r"(addr))

#define MMA_F16(d, a, b) \
    asm volatile("mma.sync.aligned.m16n8k16.row.col.f32.f16.f16.f32 " \
        "{%0,%1,%2,%3}, {%4,%5,%6,%7}, {%8,%9}, {%0,%1,%2,%3};" \
        : "+f"((d)[0]), "+f"((d)[1]), "+f"((d)[2]), "+f"((d)[3]) \
        : "r"((a)[0]), "r"((a)[1]), "r"((a)[2]), "r"((a)[3]), \
          "r"((b)[0]), "r"((b)[1]))

// ---------- f32x2 helpers for scalar kernels ----------
__device__ __forceinline__ void fma2(u64& d, u64 a, u64 b) {
    asm("fma.rn.f32x2 %0, %1, %2, %0;" : "+l"(d) : "l"(a), "l"(b));
}
__device__ __forceinline__ float2 unpack2(u64 v) {
    float2 f;
    asm("mov.b64 {%0, %1}, %2;" : "=f"(f.x), "=f"(f.y) : "l"(v));
    return f;
}
__device__ __forceinline__ u64 lds64(const float* p) {
    return *reinterpret_cast<const u64*>(p);
}

// =====================================================================
// Kernel 0 (fused prep): W1 -> half [g][co][k]; x -> float pad (copy0)
// + half pads (2 parities).
// =====================================================================
#define W1_BLOCKS 6272
#define XPH_BLOCKS ((NPC / 2 + 255) / 256)

__global__ void __launch_bounds__(256) prep_all(const float* __restrict__ W1,
                                                const float* __restrict__ x)
{
    if (blockIdx.x < W1_BLOCKS) {
        int idx = blockIdx.x * 256 + threadIdx.x;     // 392*4096
        int g = idx >> 12, e = idx & 4095;
        int co = e >> 5, k = e & 31;
        int tap = g >> 3, cib = g & 7;
        float wv = W1[((size_t)co * CC + cib * 32 + k) * NT + tap];
        g_W1bh[idx] = __float2half_rn(wv);
    } else {
        int pc = (blockIdx.x - W1_BLOCKS) * 256 + threadIdx.x;
        if (pc >= NPC / 2) return;
        int cp2 = pc % (XPR / 2);
        int col = cp2 * 2;
        int t = pc / (XPR / 2);
        int r = t % XPR;
        int bc = t / XPR;
        int rr = r - 6;
        float v0a = 0.f, v0b = 0.f, v1a = 0.f, v1b = 0.f;
        if ((unsigned)rr < HH) {
            const float* xr = x + (size_t)bc * HW + rr * WW;
            int ca = col - 6; if ((unsigned)ca < WW) v0a = __ldg(xr + ca);
            int cb = col - 5; if ((unsigned)cb < WW) v0b = __ldg(xr + cb);
            int cd = col - 4; if ((unsigned)cd < WW) v1a = __ldg(xr + cd);
            int ce = col - 3; if ((unsigned)ce < WW) v1b = __ldg(xr + ce);
        }
        size_t o = (size_t)bc * XPCH + r * XPR + col;
        *reinterpret_cast<float2*>(g_xpadf + o) = make_float2(v0a, v0b);
        *reinterpret_cast<half2*>(g_xh + o) = __floats2half2_rn(v0a, v0b);
        *reinterpret_cast<half2*>(g_xh + NPC + o) = __floats2half2_rn(v1a, v1b);
    }
}

// =====================================================================
// Kernel A: conv1 fp16 mma.m16n8k16 GEMM. Grid (49, 3), 512 threads.
// (unchanged from round 13 — proven)
// =====================================================================
#define ASTH 264
#define A_BYTES (32 * ASTH * 2)          // 16896
#define BSTH 40
#define B_BYTES (128 * BSTH * 2)         // 10240
#define NST 6
#define CST 260
#define CONV1_SMEM (NST * (A_BYTES + B_BYTES))   // 162816

__global__ void __launch_bounds__(512, 1) conv1_mma()
{
    extern __shared__ __align__(16) char smem[];
    const uint32_t sb = smem_to_u32(smem);
    const uint32_t sbB0 = sb + NST * A_BYTES;

    const int tid = threadIdx.x;
    const int wid = tid >> 5, lane = tid & 31;
    const int m0 = (wid >> 2) * 64;
    const int n0 = (wid & 3) * 32;

    const int q = blockIdx.y;
    const int gstart = (q == 0) ? 0 : (132 + 130 * (q - 1));
    const int nn = (q == 0) ? 132 : 130;

    const uint32_t arow = (lane & 7) + ((lane & 16) >> 1);
    const uint32_t acol = (lane & 8);
    const int l15 = lane & 15;
    const uint32_t brow = (l15 & 7);
    const uint32_t bk8 = (l15 & 8);

    const int kl = tid >> 6;
    const int qd = tid & 63;
    const int gp = blockIdx.x * 256 + qd * 4;
    const int b4 = gp / HW, rem4 = gp % HW;
    const int h4 = rem4 / WW, w4 = rem4 % WW;
    const __half* const aBaseH = g_xh + (size_t)(b4 * CC + kl) * XPCH
                               + h4 * XPR + w4;
    const uint32_t a_dst0 = sb + (uint32_t)(kl * ASTH + qd * 4) * 2;

    auto issue = [&](int g, int s) {
        {
            int co = tid >> 2, kq = tid & 3;
            const __half* srcB = g_W1bh + (size_t)g * 4096 + co * 32 + kq * 8;
            CP16(sbB0 + (uint32_t)s * B_BYTES + (uint32_t)(co * BSTH + kq * 8) * 2,
                 (const char*)srcB);
        }
        int tap = g >> 3, cib = g & 7;
        int di = tap / 7, dj = tap - di * 7;
        int par = dj & 1;
        const __half* sA = aBaseH + (par ? NPC : 0) + (size_t)(cib * 32) * XPCH
                         + di * (2 * XPR) + (2 * dj - 2 * par);
        uint32_t dA = a_dst0 + (uint32_t)s * A_BYTES;
#pragma unroll
        for (int it = 0; it < 4; ++it) {
            CP8(dA, (const char*)sA);
            dA += 8 * ASTH * 2;
            sA += (size_t)8 * XPCH;
        }
        CP_COMMIT();
    };

    float acc[4][4][4];
#pragma unroll
    for (int i = 0; i < 4; ++i)
#pragma unroll
        for (int j = 0; j < 4; ++j)
#pragma unroll
            for (int c = 0; c < 4; ++c) acc[i][j][c] = 0.f;

    auto compute = [&](int s) {
        const uint32_t aS = sb + (uint32_t)s * A_BYTES
                          + (arow * ASTH + m0 + acol) * 2;
        const uint32_t bS = sbB0 + (uint32_t)s * B_BYTES
                          + ((n0 + brow) * BSTH + bk8) * 2;
#pragma unroll
        for (int ks = 0; ks < 2; ++ks) {
            const uint32_t aK = aS + ks * (16 * ASTH * 2);
            const uint32_t bK = bS + ks * 32;
            uint32_t af[4][4], bf[4][2];
#pragma unroll
            for (int i = 0; i < 4; ++i) LDMX4T(af[i], aK + 32 * i);
#pragma unroll
            for (int j = 0; j < 4; ++j) LDMX2(bf[j], bK + j * (8 * BSTH * 2));
#pragma unroll
            for (int i = 0; i < 4; ++i)
#pragma unroll
                for (int j = 0; j < 4; ++j)
                    MMA_F16(acc[i][j], af[i], bf[j]);
        }
    };

    issue(gstart + 0, 0);
    issue(gstart + 1, 1);
    issue(gstart + 2, 2);
    issue(gstart + 3, 3);

    for (int gi = 0; gi < nn; gi += 2) {
        if (gi + 2 < nn) { CP_WAIT2(); } else { CP_WAIT0(); }
        __syncthreads();
        compute(gi % NST);
        compute((gi + 1) % NST);
        if (gi + 4 < nn) issue(gstart + gi + 4, (gi + 4) % NST);
        if (gi + 5 < nn) issue(gstart + gi + 5, (gi + 5) % NST);
    }
    __syncthreads();

    float* const Cs = (float*)smem;
    {
        const int g8 = lane >> 2, t4 = lane & 3;
#pragma unroll
        for (int i = 0; i < 4; ++i)
#pragma unroll
            for (int j = 0; j < 4; ++j) {
                int row0 = m0 + 16 * i + g8;
                int col0 = n0 + 8 * j + 2 * t4;
                Cs[(col0)     * CST + row0]     = acc[i][j][0];
                Cs[(col0 + 1) * CST + row0]     = acc[i][j][1];
                Cs[(col0)     * CST + row0 + 8] = acc[i][j][2];
                Cs[(col0 + 1) * CST + row0 + 8] = acc[i][j][3];
            }
    }
    __syncthreads();

    {
        const int pxl = tid & 255, ch = tid >> 8;
        const int pxg = blockIdx.x * 256 + pxl;
        const int b2 = pxg / HW, rem2 = pxg % HW;
        float* base = g_part + ((size_t)(q * BB + b2) * CO) * HW + rem2;
#pragma unroll 4
        for (int co = ch * 64; co < ch * 64 + 64; ++co)
            base[(size_t)co * HW] = Cs[co * CST + pxl];
    }
}

// =====================================================================
// Kernel B: conv2 (1x1, 128->49) + softmax, 4 lanes per pixel.
// (unchanged from round 13)
// =====================================================================
#define W2SL 1576
__global__ void __launch_bounds__(256) conv2_softmax_kernel(
    const float* __restrict__ W2, const float* __restrict__ b1,
    const float* __restrict__ b2)
{
    __shared__ float W2r[4 * W2SL];
    __shared__ float b2s[NT];
    __shared__ float b1s[CO];
    const int tid = threadIdx.x;

    for (int t = tid; t < 4 * NT * 32; t += 256) {
        int s = t / (NT * 32), r = t - s * (NT * 32);
        int kk = r >> 5, j = r & 31;
        W2r[s * W2SL + kk * 32 + j] = __ldg(&W2[kk * 128 + s * 32 + j]);
    }
    if (tid < NT) b2s[tid] = __ldg(&b2[tid]);
    if (tid < CO) b1s[tid] = __ldg(&b1[tid]);
    __syncthreads();

    const int wid = tid >> 5, lane = tid & 31;
    const int slice = lane >> 3, pl = lane & 7;
    const int px = blockIdx.x * 64 + wid * 8 + pl;
    const int b = px / HW, rem = px % HW;
    const int c0 = slice * 32;

    float acc[NT];
#pragma unroll
    for (int kk = 0; kk < NT; ++kk) acc[kk] = 0.f;

    const float* p0 = g_part + ((size_t)(0 * BB + b) * CO + c0) * HW + rem;
    const float* p1 = g_part + ((size_t)(1 * BB + b) * CO + c0) * HW + rem;
    const float* p2 = g_part + ((size_t)(2 * BB + b) * CO + c0) * HW + rem;
    const float* wbase = &W2r[slice * W2SL];

#pragma unroll 4
    for (int c = 0; c < 32; ++c) {
        float kv = p0[(size_t)c * HW] + p1[(size_t)c * HW] + p2[(size_t)c * HW]
                 + b1s[c0 + c];
        const float* wc = wbase + c;
#pragma unroll
        for (int kk = 0; kk < NT; ++kk)
            acc[kk] = fmaf(kv, wc[kk * 32], acc[kk]);
    }

#pragma unroll
    for (int kk = 0; kk < NT; ++kk) {
        acc[kk] += __shfl_xor_sync(0xffffffffu, acc[kk], 8);
        acc[kk] += __shfl_xor_sync(0xffffffffu, acc[kk], 16);
        acc[kk] += b2s[kk];
    }

    float m = acc[0];
#pragma unroll
    for (int kk = 1; kk < NT; ++kk) m = fmaxf(m, acc[kk]);
    float s = 0.f;
#pragma unroll
    for (int kk = 0; kk < NT; ++kk) {
        acc[kk] = expf(acc[kk] - m);
        s += acc[kk];
    }
    float inv = 1.f / s;

    float* dst = g_attn + (size_t)b * NT * HW + rem;
    const int k_lo = (slice == 0) ? 0 : (13 + (slice - 1) * 12);
    const int k_hi = (slice == 0) ? 13 : (k_lo + 12);
    for (int kk = k_lo; kk < k_hi; ++kk)
        dst[(size_t)kk * HW] = acc[kk] * inv;
}

// =====================================================================
// Kernel C: weighted local sum over 49 dilated taps -> out
// Grid (56, 4, 2), 224 threads. Thread = 4 channels x 2 px (4 FMA chains,
// attn amortized over 4). 32-ch x chunks (4 iters). Dynamic smem 71KB.
// =====================================================================
#define AT_ELEMS (49 * 60)
#define XS_ELEMS (224 * 68)
#define GATHER_SMEM ((AT_ELEMS + XS_ELEMS) * 4)   // 72688

__global__ void __launch_bounds__(224) gather_kernel(float* __restrict__ out)
{
    extern __shared__ __align__(16) float gsm[];
    float* const at = gsm;                 // [49][60]
    float* const xs = gsm + AT_ELEMS;      // [32*7][68]
    const int h = blockIdx.x, b = blockIdx.y;
    const int chalf = blockIdx.z * 128;
    const int tid = threadIdx.x;

    for (int t = tid; t < 49 * 14; t += 224) {
        int kk = t / 14, p4 = t - kk * 14;
        *reinterpret_cast<float4*>(&at[kk * 60 + p4 * 4]) =
            *reinterpret_cast<const float4*>(
                g_attn + ((size_t)b * NT + kk) * HW + h * WW + p4 * 4);
    }

    const int pg = tid % 28, cg = tid / 28;   // 28 px-pairs x 8 ch-quads
    const int p0 = pg * 2;
    const int c0 = cg * 4;

    for (int ch = 0; ch < 4; ++ch) {
        __syncthreads();
        // x tile: 32 ch x 7 rows x 68 cols, guard-free from padded image
        const float* xpc = g_xpadf + (size_t)(b * CC + chalf + ch * 32) * XPCH
                         + (size_t)h * XPR;
        for (int t = tid; t < 32 * 7 * 17; t += 224) {
            int c = t / 119;
            int r = t - c * 119;
            int i = r / 17;
            int qd = r - i * 17;
            *reinterpret_cast<float4*>(&xs[(c * 7 + i) * 68 + qd * 4]) =
                *reinterpret_cast<const float4*>(xpc + (size_t)c * XPCH
                                                 + i * (2 * XPR) + qd * 4);
        }
        __syncthreads();

        u64 a0 = 0ull, a1 = 0ull, a2 = 0ull, a3 = 0ull;
#pragma unroll
        for (int i = 0; i < 7; ++i) {
            const float* xr0 = &xs[((c0 + 0) * 7 + i) * 68 + p0];
            const float* xr1 = &xs[((c0 + 1) * 7 + i) * 68 + p0];
            const float* xr2 = &xs[((c0 + 2) * 7 + i) * 68 + p0];
            const float* xr3 = &xs[((c0 + 3) * 7 + i) * 68 + p0];
            const float* ar = &at[(i * 7) * 60 + p0];
#pragma unroll
            for (int j = 0; j < 7; ++j) {
                u64 av = lds64(ar + j * 60);
                fma2(a0, av, lds64(xr0 + 2 * j));
                fma2(a1, av, lds64(xr1 + 2 * j));
                fma2(a2, av, lds64(xr2 + 2 * j));
                fma2(a3, av, lds64(xr3 + 2 * j));
            }
        }
        size_t ob = (size_t)(b * CC + chalf + ch * 32 + c0) * HW + h * WW + p0;
        *reinterpret_cast<float2*>(&out[ob])          = unpack2(a0);
        *reinterpret_cast<float2*>(&out[ob + HW])     = unpack2(a1);
        *reinterpret_cast<float2*>(&out[ob + 2 * HW]) = unpack2(a2);
        *reinterpret_cast<float2*>(&out[ob + 3 * HW]) = unpack2(a3);
    }
}

// =====================================================================
extern "C" void kernel_launch(void* const* d_in, const int* in_sizes, int n_in,
                              void* d_out, int out_size)
{
    const float* x  = (const float*)d_in[0];
    const float* W1 = (const float*)d_in[1];
    const float* b1 = (const float*)d_in[2];
    const float* W2 = (const float*)d_in[3];
    const float* b2 = (const float*)d_in[4];
    for (int i = 0; i < n_in; ++i) {
        switch (in_sizes[i]) {
            case BB * CC * HW: x  = (const float*)d_in[i]; break;
            case CO * CC * NT: W1 = (const float*)d_in[i]; break;
            case CO:           b1 = (const float*)d_in[i]; break;
            case NT * CO:      W2 = (const float*)d_in[i]; break;
            case NT:           b2 = (const float*)d_in[i]; break;
            default: break;
        }
    }
    float* out = (float*)d_out;

    cudaFuncSetAttribute(conv1_mma, cudaFuncAttributeMaxDynamicSharedMemorySize,
                         CONV1_SMEM);
    cudaFuncSetAttribute(gather_kernel, cudaFuncAttributeMaxDynamicSharedMemorySize,
                         GATHER_SMEM);
    prep_all<<<W1_BLOCKS + XPH_BLOCKS, 256>>>(W1, x);
    conv1_mma<<<dim3(49, KSPL), 512, CONV1_SMEM>>>();
    conv2_softmax_kernel<<<196, 256>>>(W2, b1, b2);
    gather_kernel<<<dim3(56, 4, 2), 224, GATHER_SMEM>>>(out);
}

// round 15
// speedup vs baseline: 1.0551x; 1.0551x over previous
#include <cuda_runtime.h>
#include <cuda_fp16.h>
#include <cstdint>

#define BB 4
#define CC 256
#define HH 56
#define WW 56
#define CO 128
#define NT 49
#define HW 3136
#define GTOT 392          // 49 taps x 8 ci-blocks of 32
#define KSPL 3
#define XPR 68            // padded image 68x68
#define XPCH (XPR * XPR)  // 4624
#define NPC (BB * CC * XPCH)

typedef unsigned long long u64;

// ---- device-global scratch ----
__device__ __align__(16) __half g_W1bh[GTOT * 4096];         // half weights [g][co][k]
__device__ __align__(16) float  g_xpadf[NPC];                // padded x float (gather)
__device__ __align__(16) __half g_xh[2 * NPC];               // padded x half, 2 parities
__device__ __align__(16) __half g_parth[KSPL * BB * CO * HW];// conv1 K-split partials (fp16)
__device__ __align__(16) float  g_attn[BB * NT * HW];        // softmax attention

// ---------- helpers ----------
__device__ __forceinline__ uint32_t smem_to_u32(const void* p) {
    uint32_t a;
    asm("{ .reg .u64 t; cvta.to.shared.u64 t, %1; cvt.u32.u64 %0, t; }" : "=r"(a) : "l"(p));
    return a;
}
#define CP16(dst, src) \
    asm volatile("cp.async.cg.shared.global [%0], [%1], 16;" :: "r"(dst), "l"(src) : "memory")
#define CP8(dst, src) \
    asm volatile("cp.async.ca.shared.global [%0], [%1], 8;" :: "r"(dst), "l"(src) : "memory")
#define CP_COMMIT() asm volatile("cp.async.commit_group;" ::: "memory")
#define CP_WAIT0()  asm volatile("cp.async.wait_group 0;" ::: "memory")
#define CP_WAIT2()  asm volatile("cp.async.wait_group 2;" ::: "memory")

#define LDMX4T(r, addr) \
    asm volatile("ldmatrix.sync.aligned.m8n8.x4.trans.shared.b16 {%0,%1,%2,%3}, [%4];" \
        : "=r"((r)[0]), "=r"((r)[1]), "=r"((r)[2]), "=r"((r)[3]) : "r"(addr))
#define LDMX2(r, addr) \
    asm volatile("ldmatrix.sync.aligned.m8n8.x2.shared.b16 {%0,%1}, [%2];" \
        : "=r"((r)[0]), "=r"((r)[1]) : "r"(addr))

#define MMA_F16(d, a, b) \
    asm volatile("mma.sync.aligned.m16n8k16.row.col.f32.f16.f16.f32 " \
        "{%0,%1,%2,%3}, {%4,%5,%6,%7}, {%8,%9}, {%0,%1,%2,%3};" \
        : "+f"((d)[0]), "+f"((d)[1]), "+f"((d)[2]), "+f"((d)[3]) \
        : "r"((a)[0]), "r"((a)[1]), "r"((a)[2]), "r"((a)[3]), \
          "r"((b)[0]), "r"((b)[1]))

// ---------- f32x2 helpers for scalar kernels ----------
__device__ __forceinline__ void fma2(u64& d, u64 a, u64 b) {
    asm("fma.rn.f32x2 %0, %1, %2, %0;" : "+l"(d) : "l"(a), "l"(b));
}
__device__ __forceinline__ float2 unpack2(u64 v) {
    float2 f;
    asm("mov.b64 {%0, %1}, %2;" : "=f"(f.x), "=f"(f.y) : "l"(v));
    return f;
}
__device__ __forceinline__ u64 lds64(const float* p) {
    return *reinterpret_cast<const u64*>(p);
}

// =====================================================================
// Kernel 0 (fused prep): W1 -> half [g][co][k]; x -> float pad (copy0)
// + half pads (2 parities).
// =====================================================================
#define W1_BLOCKS 6272
#define XPH_BLOCKS ((NPC / 2 + 255) / 256)

__global__ void __launch_bounds__(256) prep_all(const float* __restrict__ W1,
                                                const float* __restrict__ x)
{
    if (blockIdx.x < W1_BLOCKS) {
        int idx = blockIdx.x * 256 + threadIdx.x;     // 392*4096
        int g = idx >> 12, e = idx & 4095;
        int co = e >> 5, k = e & 31;
        int tap = g >> 3, cib = g & 7;
        float wv = W1[((size_t)co * CC + cib * 32 + k) * NT + tap];
        g_W1bh[idx] = __float2half_rn(wv);
    } else {
        int pc = (blockIdx.x - W1_BLOCKS) * 256 + threadIdx.x;
        if (pc >= NPC / 2) return;
        int cp2 = pc % (XPR / 2);
        int col = cp2 * 2;
        int t = pc / (XPR / 2);
        int r = t % XPR;
        int bc = t / XPR;
        int rr = r - 6;
        float v0a = 0.f, v0b = 0.f, v1a = 0.f, v1b = 0.f;
        if ((unsigned)rr < HH) {
            const float* xr = x + (size_t)bc * HW + rr * WW;
            int ca = col - 6; if ((unsigned)ca < WW) v0a = __ldg(xr + ca);
            int cb = col - 5; if ((unsigned)cb < WW) v0b = __ldg(xr + cb);
            int cd = col - 4; if ((unsigned)cd < WW) v1a = __ldg(xr + cd);
            int ce = col - 3; if ((unsigned)ce < WW) v1b = __ldg(xr + ce);
        }
        size_t o = (size_t)bc * XPCH + r * XPR + col;
        *reinterpret_cast<float2*>(g_xpadf + o) = make_float2(v0a, v0b);
        *reinterpret_cast<half2*>(g_xh + o) = __floats2half2_rn(v0a, v0b);
        *reinterpret_cast<half2*>(g_xh + NPC + o) = __floats2half2_rn(v1a, v1b);
    }
}

// =====================================================================
// Kernel A: conv1 fp16 mma.m16n8k16 GEMM. Grid (49, 3), 512 threads.
// (mainloop unchanged from round 13; epilogue stores fp16 partials)
// =====================================================================
#define ASTH 264
#define A_BYTES (32 * ASTH * 2)          // 16896
#define BSTH 40
#define B_BYTES (128 * BSTH * 2)         // 10240
#define NST 6
#define CST 260
#define CONV1_SMEM (NST * (A_BYTES + B_BYTES))   // 162816

__global__ void __launch_bounds__(512, 1) conv1_mma()
{
    extern __shared__ __align__(16) char smem[];
    const uint32_t sb = smem_to_u32(smem);
    const uint32_t sbB0 = sb + NST * A_BYTES;

    const int tid = threadIdx.x;
    const int wid = tid >> 5, lane = tid & 31;
    const int m0 = (wid >> 2) * 64;
    const int n0 = (wid & 3) * 32;

    const int q = blockIdx.y;
    const int gstart = (q == 0) ? 0 : (132 + 130 * (q - 1));
    const int nn = (q == 0) ? 132 : 130;

    const uint32_t arow = (lane & 7) + ((lane & 16) >> 1);
    const uint32_t acol = (lane & 8);
    const int l15 = lane & 15;
    const uint32_t brow = (l15 & 7);
    const uint32_t bk8 = (l15 & 8);

    const int kl = tid >> 6;
    const int qd = tid & 63;
    const int gp = blockIdx.x * 256 + qd * 4;
    const int b4 = gp / HW, rem4 = gp % HW;
    const int h4 = rem4 / WW, w4 = rem4 % WW;
    const __half* const aBaseH = g_xh + (size_t)(b4 * CC + kl) * XPCH
                               + h4 * XPR + w4;
    const uint32_t a_dst0 = sb + (uint32_t)(kl * ASTH + qd * 4) * 2;

    auto issue = [&](int g, int s) {
        {
            int co = tid >> 2, kq = tid & 3;
            const __half* srcB = g_W1bh + (size_t)g * 4096 + co * 32 + kq * 8;
            CP16(sbB0 + (uint32_t)s * B_BYTES + (uint32_t)(co * BSTH + kq * 8) * 2,
                 (const char*)srcB);
        }
        int tap = g >> 3, cib = g & 7;
        int di = tap / 7, dj = tap - di * 7;
        int par = dj & 1;
        const __half* sA = aBaseH + (par ? NPC : 0) + (size_t)(cib * 32) * XPCH
                         + di * (2 * XPR) + (2 * dj - 2 * par);
        uint32_t dA = a_dst0 + (uint32_t)s * A_BYTES;
#pragma unroll
        for (int it = 0; it < 4; ++it) {
            CP8(dA, (const char*)sA);
            dA += 8 * ASTH * 2;
            sA += (size_t)8 * XPCH;
        }
        CP_COMMIT();
    };

    float acc[4][4][4];
#pragma unroll
    for (int i = 0; i < 4; ++i)
#pragma unroll
        for (int j = 0; j < 4; ++j)
#pragma unroll
            for (int c = 0; c < 4; ++c) acc[i][j][c] = 0.f;

    auto compute = [&](int s) {
        const uint32_t aS = sb + (uint32_t)s * A_BYTES
                          + (arow * ASTH + m0 + acol) * 2;
        const uint32_t bS = sbB0 + (uint32_t)s * B_BYTES
                          + ((n0 + brow) * BSTH + bk8) * 2;
#pragma unroll
        for (int ks = 0; ks < 2; ++ks) {
            const uint32_t aK = aS + ks * (16 * ASTH * 2);
            const uint32_t bK = bS + ks * 32;
            uint32_t af[4][4], bf[4][2];
#pragma unroll
            for (int i = 0; i < 4; ++i) LDMX4T(af[i], aK + 32 * i);
#pragma unroll
            for (int j = 0; j < 4; ++j) LDMX2(bf[j], bK + j * (8 * BSTH * 2));
#pragma unroll
            for (int i = 0; i < 4; ++i)
#pragma unroll
                for (int j = 0; j < 4; ++j)
                    MMA_F16(acc[i][j], af[i], bf[j]);
        }
    };

    issue(gstart + 0, 0);
    issue(gstart + 1, 1);
    issue(gstart + 2, 2);
    issue(gstart + 3, 3);

    for (int gi = 0; gi < nn; gi += 2) {
        if (gi + 2 < nn) { CP_WAIT2(); } else { CP_WAIT0(); }
        __syncthreads();
        compute(gi % NST);
        compute((gi + 1) % NST);
        if (gi + 4 < nn) issue(gstart + gi + 4, (gi + 4) % NST);
        if (gi + 5 < nn) issue(gstart + gi + 5, (gi + 5) % NST);
    }
    __syncthreads();

    float* const Cs = (float*)smem;
    {
        const int g8 = lane >> 2, t4 = lane & 3;
#pragma unroll
        for (int i = 0; i < 4; ++i)
#pragma unroll
            for (int j = 0; j < 4; ++j) {
                int row0 = m0 + 16 * i + g8;
                int col0 = n0 + 8 * j + 2 * t4;
                Cs[(col0)     * CST + row0]     = acc[i][j][0];
                Cs[(col0 + 1) * CST + row0]     = acc[i][j][1];
                Cs[(col0)     * CST + row0 + 8] = acc[i][j][2];
                Cs[(col0 + 1) * CST + row0 + 8] = acc[i][j][3];
            }
    }
    __syncthreads();

    {
        const int pxl = tid & 255, ch = tid >> 8;
        const int pxg = blockIdx.x * 256 + pxl;
        const int b2 = pxg / HW, rem2 = pxg % HW;
        __half* base = g_parth + ((size_t)(q * BB + b2) * CO) * HW + rem2;
#pragma unroll 4
        for (int co = ch * 64; co < ch * 64 + 64; ++co)
            base[(size_t)co * HW] = __float2half_rn(Cs[co * CST + pxl]);
    }
}

// =====================================================================
// Kernel B: conv2 (1x1, 128->49) + softmax, 4 lanes per pixel.
// Partials now fp16 (half the load bytes).
// =====================================================================
#define W2SL 1576
__global__ void __launch_bounds__(256) conv2_softmax_kernel(
    const float* __restrict__ W2, const float* __restrict__ b1,
    const float* __restrict__ b2)
{
    __shared__ float W2r[4 * W2SL];
    __shared__ float b2s[NT];
    __shared__ float b1s[CO];
    const int tid = threadIdx.x;

    for (int t = tid; t < 4 * NT * 32; t += 256) {
        int s = t / (NT * 32), r = t - s * (NT * 32);
        int kk = r >> 5, j = r & 31;
        W2r[s * W2SL + kk * 32 + j] = __ldg(&W2[kk * 128 + s * 32 + j]);
    }
    if (tid < NT) b2s[tid] = __ldg(&b2[tid]);
    if (tid < CO) b1s[tid] = __ldg(&b1[tid]);
    __syncthreads();

    const int wid = tid >> 5, lane = tid & 31;
    const int slice = lane >> 3, pl = lane & 7;
    const int px = blockIdx.x * 64 + wid * 8 + pl;
    const int b = px / HW, rem = px % HW;
    const int c0 = slice * 32;

    float acc[NT];
#pragma unroll
    for (int kk = 0; kk < NT; ++kk) acc[kk] = 0.f;

    const __half* p0 = g_parth + ((size_t)(0 * BB + b) * CO + c0) * HW + rem;
    const __half* p1 = g_parth + ((size_t)(1 * BB + b) * CO + c0) * HW + rem;
    const __half* p2 = g_parth + ((size_t)(2 * BB + b) * CO + c0) * HW + rem;
    const float* wbase = &W2r[slice * W2SL];

#pragma unroll 4
    for (int c = 0; c < 32; ++c) {
        float kv = __half2float(p0[(size_t)c * HW])
                 + __half2float(p1[(size_t)c * HW])
                 + __half2float(p2[(size_t)c * HW])
                 + b1s[c0 + c];
        const float* wc = wbase + c;
#pragma unroll
        for (int kk = 0; kk < NT; ++kk)
            acc[kk] = fmaf(kv, wc[kk * 32], acc[kk]);
    }

#pragma unroll
    for (int kk = 0; kk < NT; ++kk) {
        acc[kk] += __shfl_xor_sync(0xffffffffu, acc[kk], 8);
        acc[kk] += __shfl_xor_sync(0xffffffffu, acc[kk], 16);
        acc[kk] += b2s[kk];
    }

    float m = acc[0];
#pragma unroll
    for (int kk = 1; kk < NT; ++kk) m = fmaxf(m, acc[kk]);
    float s = 0.f;
#pragma unroll
    for (int kk = 0; kk < NT; ++kk) {
        acc[kk] = expf(acc[kk] - m);
        s += acc[kk];
    }
    float inv = 1.f / s;

    float* dst = g_attn + (size_t)b * NT * HW + rem;
    const int k_lo = (slice == 0) ? 0 : (13 + (slice - 1) * 12);
    const int k_hi = (slice == 0) ? 13 : (k_lo + 12);
    for (int kk = k_lo; kk < k_hi; ++kk)
        dst[(size_t)kk * HW] = acc[kk] * inv;
}

// =====================================================================
// Kernel C: weighted local sum over 49 dilated taps -> out
// Grid (56, 4, 2), 224 threads. Thread = 2 channels x 2 px.
// 16-ch chunks, DOUBLE-BUFFERED via cp.async (loads hide under compute).
// =====================================================================
#define GNCH 16
#define XS_W (GNCH * 7 * 68)                 // 7616 floats per buffer
#define AT_ELEMS (49 * 60)
#define GATHER_SMEM ((AT_ELEMS + 2 * XS_W) * 4)   // 72688

__global__ void __launch_bounds__(224) gather_kernel(float* __restrict__ out)
{
    extern __shared__ __align__(16) float gsm[];
    float* const at = gsm;                    // [49][60]
    float* const xs0 = gsm + AT_ELEMS;        // two x buffers
    const int h = blockIdx.x, b = blockIdx.y;
    const int chalf = blockIdx.z * 128;
    const int tid = threadIdx.x;
    const uint32_t xs_sb = smem_to_u32(xs0);

    // attn tile (regular loads; covered by first barrier)
    for (int t = tid; t < 49 * 14; t += 224) {
        int kk = t / 14, p4 = t - kk * 14;
        *reinterpret_cast<float4*>(&at[kk * 60 + p4 * 4]) =
            *reinterpret_cast<const float4*>(
                g_attn + ((size_t)b * NT + kk) * HW + h * WW + p4 * 4);
    }

    // x chunk issue: 16 ch x 7 rows x 17 float4 = 1904 chunks
    auto issueX = [&](int ch, int buf) {
        const float* xpc = g_xpadf + (size_t)(b * CC + chalf + ch * GNCH) * XPCH
                         + (size_t)h * XPR;
        const uint32_t dstb = xs_sb + (uint32_t)buf * (XS_W * 4);
#pragma unroll
        for (int it = 0; it < 9; ++it) {
            int t = tid + it * 224;
            if (t < GNCH * 7 * 17) {
                int c = t / 119;
                int r = t - c * 119;
                int i = r / 17;
                int qd = r - i * 17;
                CP16(dstb + (uint32_t)((c * 7 + i) * 68 + qd * 4) * 4,
                     (const char*)(xpc + (size_t)c * XPCH + i * (2 * XPR) + qd * 4));
            }
        }
        CP_COMMIT();
    };

    const int pg = tid % 28, cg = tid / 28;   // 28 px-pairs x 8 ch-pairs
    const int p0 = pg * 2;
    const int c0 = cg * 2, c1 = c0 + 1;

    issueX(0, 0);

    for (int ch = 0; ch < 8; ++ch) {
        CP_WAIT0();
        __syncthreads();                        // chunk ch visible; prev compute done
        if (ch + 1 < 8) issueX(ch + 1, (ch + 1) & 1);

        const float* xb = xs0 + (ch & 1) * XS_W;
        u64 a0 = 0ull, a1 = 0ull;
#pragma unroll
        for (int i = 0; i < 7; ++i) {
            const float* xr0 = &xb[(c0 * 7 + i) * 68 + p0];
            const float* xr1 = &xb[(c1 * 7 + i) * 68 + p0];
            const float* ar = &at[(i * 7) * 60 + p0];
#pragma unroll
            for (int j = 0; j < 7; ++j) {
                u64 av = lds64(ar + j * 60);
                fma2(a0, av, lds64(xr0 + 2 * j));
                fma2(a1, av, lds64(xr1 + 2 * j));
            }
        }
        size_t ob = (size_t)(b * CC + chalf + ch * GNCH + c0) * HW + h * WW + p0;
        *reinterpret_cast<float2*>(&out[ob])      = unpack2(a0);
        *reinterpret_cast<float2*>(&out[ob + HW]) = unpack2(a1);
        __syncthreads();                        // compute done before buffer reuse
    }
}

// =====================================================================
extern "C" void kernel_launch(void* const* d_in, const int* in_sizes, int n_in,
                              void* d_out, int out_size)
{
    const float* x  = (const float*)d_in[0];
    const float* W1 = (const float*)d_in[1];
    const float* b1 = (const float*)d_in[2];
    const float* W2 = (const float*)d_in[3];
    const float* b2 = (const float*)d_in[4];
    for (int i = 0; i < n_in; ++i) {
        switch (in_sizes[i]) {
            case BB * CC * HW: x  = (const float*)d_in[i]; break;
            case CO * CC * NT: W1 = (const float*)d_in[i]; break;
            case CO:           b1 = (const float*)d_in[i]; break;
            case NT * CO:      W2 = (const float*)d_in[i]; break;
            case NT:           b2 = (const float*)d_in[i]; break;
            default: break;
        }
    }
    float* out = (float*)d_out;

    cudaFuncSetAttribute(conv1_mma, cudaFuncAttributeMaxDynamicSharedMemorySize,
                         CONV1_SMEM);
    cudaFuncSetAttribute(gather_kernel, cudaFuncAttributeMaxDynamicSharedMemorySize,
                         GATHER_SMEM);
    prep_all<<<W1_BLOCKS + XPH_BLOCKS, 256>>>(W1, x);
    conv1_mma<<<dim3(49, KSPL), 512, CONV1_SMEM>>>();
    conv2_softmax_kernel<<<196, 256>>>(W2, b1, b2);
    gather_kernel<<<dim3(56, 4, 2), 224, GATHER_SMEM>>>(out);
}

// round 16
// speedup vs baseline: 1.1422x; 1.0826x over previous
#include <cuda_runtime.h>
#include <cuda_fp16.h>
#include <cstdint>

#define BB 4
#define CC 256
#define HH 56
#define WW 56
#define CO 128
#define NT 49
#define HW 3136
#define GTOT 392          // 49 taps x 8 ci-blocks of 32
#define KSPL 3
#define XPR 68            // padded image 68x68
#define XPCH (XPR * XPR)  // 4624
#define NPC (BB * CC * XPCH)

typedef unsigned long long u64;

// ---- device-global scratch ----
__device__ __align__(16) __half g_W1bh[GTOT * 4096];         // half weights [g][co][k]
__device__ __align__(16) __half g_xh[2 * NPC];               // padded x half, 2 parities
__device__ __align__(16) __half g_parth[KSPL * BB * CO * HW];// conv1 K-split partials (fp16)
__device__ __align__(16) float  g_attn[BB * NT * HW];        // softmax attention

// ---------- helpers ----------
__device__ __forceinline__ uint32_t smem_to_u32(const void* p) {
    uint32_t a;
    asm("{ .reg .u64 t; cvta.to.shared.u64 t, %1; cvt.u32.u64 %0, t; }" : "=r"(a) : "l"(p));
    return a;
}
#define CP16(dst, src) \
    asm volatile("cp.async.cg.shared.global [%0], [%1], 16;" :: "r"(dst), "l"(src) : "memory")
#define CP8(dst, src) \
    asm volatile("cp.async.ca.shared.global [%0], [%1], 8;" :: "r"(dst), "l"(src) : "memory")
#define CP_COMMIT() asm volatile("cp.async.commit_group;" ::: "memory")
#define CP_WAIT0()  asm volatile("cp.async.wait_group 0;" ::: "memory")
#define CP_WAIT2()  asm volatile("cp.async.wait_group 2;" ::: "memory")

#define LDMX4T(r, addr) \
    asm volatile("ldmatrix.sync.aligned.m8n8.x4.trans.shared.b16 {%0,%1,%2,%3}, [%4];" \
        : "=r"((r)[0]), "=r"((r)[1]), "=r"((r)[2]), "=r"((r)[3]) : "r"(addr))
#define LDMX2(r, addr) \
    asm volatile("ldmatrix.sync.aligned.m8n8.x2.shared.b16 {%0,%1}, [%2];" \
        : "=r"((r)[0]), "=r"((r)[1]) : "r"(addr))

#define MMA_F16(d, a, b) \
    asm volatile("mma.sync.aligned.m16n8k16.row.col.f32.f16.f16.f32 " \
        "{%0,%1,%2,%3}, {%4,%5,%6,%7}, {%8,%9}, {%0,%1,%2,%3};" \
        : "+f"((d)[0]), "+f"((d)[1]), "+f"((d)[2]), "+f"((d)[3]) \
        : "r"((a)[0]), "r"((a)[1]), "r"((a)[2]), "r"((a)[3]), \
          "r"((b)[0]), "r"((b)[1]))

// ---------- f32x2 helpers for scalar kernels ----------
__device__ __forceinline__ void fma2(u64& d, u64 a, u64 b) {
    asm("fma.rn.f32x2 %0, %1, %2, %0;" : "+l"(d) : "l"(a), "l"(b));
}
__device__ __forceinline__ float2 unpack2(u64 v) {
    float2 f;
    asm("mov.b64 {%0, %1}, %2;" : "=f"(f.x), "=f"(f.y) : "l"(v));
    return f;
}
__device__ __forceinline__ u64 pack2f(float2 f) {
    u64 r;
    asm("mov.b64 %0, {%1, %2};" : "=l"(r) : "f"(f.x), "f"(f.y));
    return r;
}
__device__ __forceinline__ u64 lds64(const float* p) {
    return *reinterpret_cast<const u64*>(p);
}

// =====================================================================
// Kernel 0 (fused prep): blockIdx < 1024 -> W1 transpose-bake (coalesced);
// else -> zero-padded half x images (2 parities).
// =====================================================================
#define W1T_BLOCKS 1024
#define XPH_BLOCKS ((NPC / 2 + 255) / 256)

__global__ void __launch_bounds__(256) prep_all(const float* __restrict__ W1,
                                                const float* __restrict__ x)
{
    __shared__ float ws[1568];
    if (blockIdx.x < W1T_BLOCKS) {
        // one (co, cib) pair: read 1568 consecutive floats, transpose-write
        const int co = blockIdx.x >> 3, cib = blockIdx.x & 7;
        const float* src = W1 + ((size_t)co * CC + cib * 32) * NT;   // 32 ci x 49 tap
        for (int t = threadIdx.x; t < 1568; t += 256) ws[t] = __ldg(src + t);
        __syncthreads();
        for (int t = threadIdx.x; t < 1568; t += 256) {
            int tap = t >> 5, k = t & 31;
            g_W1bh[(size_t)(tap * 8 + cib) * 4096 + co * 32 + k] =
                __float2half_rn(ws[k * NT + tap]);
        }
    } else {
        int pc = (blockIdx.x - W1T_BLOCKS) * 256 + threadIdx.x;
        if (pc >= NPC / 2) return;
        int cp2 = pc % (XPR / 2);
        int col = cp2 * 2;
        int t = pc / (XPR / 2);
        int r = t % XPR;
        int bc = t / XPR;
        int rr = r - 6;
        float v0a = 0.f, v0b = 0.f, v1a = 0.f, v1b = 0.f;
        if ((unsigned)rr < HH) {
            const float* xr = x + (size_t)bc * HW + rr * WW;
            int ca = col - 6; if ((unsigned)ca < WW) v0a = __ldg(xr + ca);
            int cb = col - 5; if ((unsigned)cb < WW) v0b = __ldg(xr + cb);
            int cd = col - 4; if ((unsigned)cd < WW) v1a = __ldg(xr + cd);
            int ce = col - 3; if ((unsigned)ce < WW) v1b = __ldg(xr + ce);
        }
        size_t o = (size_t)bc * XPCH + r * XPR + col;
        *reinterpret_cast<half2*>(g_xh + o) = __floats2half2_rn(v0a, v0b);
        *reinterpret_cast<half2*>(g_xh + NPC + o) = __floats2half2_rn(v1a, v1b);
    }
}

// =====================================================================
// Kernel A: conv1 fp16 mma.m16n8k16 GEMM. Grid (49, 3), 512 threads.
// (unchanged from round 15 — proven)
// =====================================================================
#define ASTH 264
#define A_BYTES (32 * ASTH * 2)          // 16896
#define BSTH 40
#define B_BYTES (128 * BSTH * 2)         // 10240
#define NST 6
#define CST 260
#define CONV1_SMEM (NST * (A_BYTES + B_BYTES))   // 162816

__global__ void __launch_bounds__(512, 1) conv1_mma()
{
    extern __shared__ __align__(16) char smem[];
    const uint32_t sb = smem_to_u32(smem);
    const uint32_t sbB0 = sb + NST * A_BYTES;

    const int tid = threadIdx.x;
    const int wid = tid >> 5, lane = tid & 31;
    const int m0 = (wid >> 2) * 64;
    const int n0 = (wid & 3) * 32;

    const int q = blockIdx.y;
    const int gstart = (q == 0) ? 0 : (132 + 130 * (q - 1));
    const int nn = (q == 0) ? 132 : 130;

    const uint32_t arow = (lane & 7) + ((lane & 16) >> 1);
    const uint32_t acol = (lane & 8);
    const int l15 = lane & 15;
    const uint32_t brow = (l15 & 7);
    const uint32_t bk8 = (l15 & 8);

    const int kl = tid >> 6;
    const int qd = tid & 63;
    const int gp = blockIdx.x * 256 + qd * 4;
    const int b4 = gp / HW, rem4 = gp % HW;
    const int h4 = rem4 / WW, w4 = rem4 % WW;
    const __half* const aBaseH = g_xh + (size_t)(b4 * CC + kl) * XPCH
                               + h4 * XPR + w4;
    const uint32_t a_dst0 = sb + (uint32_t)(kl * ASTH + qd * 4) * 2;

    auto issue = [&](int g, int s) {
        {
            int co = tid >> 2, kq = tid & 3;
            const __half* srcB = g_W1bh + (size_t)g * 4096 + co * 32 + kq * 8;
            CP16(sbB0 + (uint32_t)s * B_BYTES + (uint32_t)(co * BSTH + kq * 8) * 2,
                 (const char*)srcB);
        }
        int tap = g >> 3, cib = g & 7;
        int di = tap / 7, dj = tap - di * 7;
        int par = dj & 1;
        const __half* sA = aBaseH + (par ? NPC : 0) + (size_t)(cib * 32) * XPCH
                         + di * (2 * XPR) + (2 * dj - 2 * par);
        uint32_t dA = a_dst0 + (uint32_t)s * A_BYTES;
#pragma unroll
        for (int it = 0; it < 4; ++it) {
            CP8(dA, (const char*)sA);
            dA += 8 * ASTH * 2;
            sA += (size_t)8 * XPCH;
        }
        CP_COMMIT();
    };

    float acc[4][4][4];
#pragma unroll
    for (int i = 0; i < 4; ++i)
#pragma unroll
        for (int j = 0; j < 4; ++j)
#pragma unroll
            for (int c = 0; c < 4; ++c) acc[i][j][c] = 0.f;

    auto compute = [&](int s) {
        const uint32_t aS = sb + (uint32_t)s * A_BYTES
                          + (arow * ASTH + m0 + acol) * 2;
        const uint32_t bS = sbB0 + (uint32_t)s * B_BYTES
                          + ((n0 + brow) * BSTH + bk8) * 2;
#pragma unroll
        for (int ks = 0; ks < 2; ++ks) {
            const uint32_t aK = aS + ks * (16 * ASTH * 2);
            const uint32_t bK = bS + ks * 32;
            uint32_t af[4][4], bf[4][2];
#pragma unroll
            for (int i = 0; i < 4; ++i) LDMX4T(af[i], aK + 32 * i);
#pragma unroll
            for (int j = 0; j < 4; ++j) LDMX2(bf[j], bK + j * (8 * BSTH * 2));
#pragma unroll
            for (int i = 0; i < 4; ++i)
#pragma unroll
                for (int j = 0; j < 4; ++j)
                    MMA_F16(acc[i][j], af[i], bf[j]);
        }
    };

    issue(gstart + 0, 0);
    issue(gstart + 1, 1);
    issue(gstart + 2, 2);
    issue(gstart + 3, 3);

    for (int gi = 0; gi < nn; gi += 2) {
        if (gi + 2 < nn) { CP_WAIT2(); } else { CP_WAIT0(); }
        __syncthreads();
        compute(gi % NST);
        compute((gi + 1) % NST);
        if (gi + 4 < nn) issue(gstart + gi + 4, (gi + 4) % NST);
        if (gi + 5 < nn) issue(gstart + gi + 5, (gi + 5) % NST);
    }
    __syncthreads();

    float* const Cs = (float*)smem;
    {
        const int g8 = lane >> 2, t4 = lane & 3;
#pragma unroll
        for (int i = 0; i < 4; ++i)
#pragma unroll
            for (int j = 0; j < 4; ++j) {
                int row0 = m0 + 16 * i + g8;
                int col0 = n0 + 8 * j + 2 * t4;
                Cs[(col0)     * CST + row0]     = acc[i][j][0];
                Cs[(col0 + 1) * CST + row0]     = acc[i][j][1];
                Cs[(col0)     * CST + row0 + 8] = acc[i][j][2];
                Cs[(col0 + 1) * CST + row0 + 8] = acc[i][j][3];
            }
    }
    __syncthreads();

    {
        const int pxl = tid & 255, ch = tid >> 8;
        const int pxg = blockIdx.x * 256 + pxl;
        const int b2 = pxg / HW, rem2 = pxg % HW;
        __half* base = g_parth + ((size_t)(q * BB + b2) * CO) * HW + rem2;
#pragma unroll 4
        for (int co = ch * 64; co < ch * 64 + 64; ++co)
            base[(size_t)co * HW] = __float2half_rn(Cs[co * CST + pxl]);
    }
}

// =====================================================================
// Kernel B: conv2 (1x1, 128->49) + softmax, 4 lanes per pixel.
// (unchanged from round 15)
// =====================================================================
#define W2SL 1576
__global__ void __launch_bounds__(256) conv2_softmax_kernel(
    const float* __restrict__ W2, const float* __restrict__ b1,
    const float* __restrict__ b2)
{
    __shared__ float W2r[4 * W2SL];
    __shared__ float b2s[NT];
    __shared__ float b1s[CO];
    const int tid = threadIdx.x;

    for (int t = tid; t < 4 * NT * 32; t += 256) {
        int s = t / (NT * 32), r = t - s * (NT * 32);
        int kk = r >> 5, j = r & 31;
        W2r[s * W2SL + kk * 32 + j] = __ldg(&W2[kk * 128 + s * 32 + j]);
    }
    if (tid < NT) b2s[tid] = __ldg(&b2[tid]);
    if (tid < CO) b1s[tid] = __ldg(&b1[tid]);
    __syncthreads();

    const int wid = tid >> 5, lane = tid & 31;
    const int slice = lane >> 3, pl = lane & 7;
    const int px = blockIdx.x * 64 + wid * 8 + pl;
    const int b = px / HW, rem = px % HW;
    const int c0 = slice * 32;

    float acc[NT];
#pragma unroll
    for (int kk = 0; kk < NT; ++kk) acc[kk] = 0.f;

    const __half* p0 = g_parth + ((size_t)(0 * BB + b) * CO + c0) * HW + rem;
    const __half* p1 = g_parth + ((size_t)(1 * BB + b) * CO + c0) * HW + rem;
    const __half* p2 = g_parth + ((size_t)(2 * BB + b) * CO + c0) * HW + rem;
    const float* wbase = &W2r[slice * W2SL];

#pragma unroll 4
    for (int c = 0; c < 32; ++c) {
        float kv = __half2float(p0[(size_t)c * HW])
                 + __half2float(p1[(size_t)c * HW])
                 + __half2float(p2[(size_t)c * HW])
                 + b1s[c0 + c];
        const float* wc = wbase + c;
#pragma unroll
        for (int kk = 0; kk < NT; ++kk)
            acc[kk] = fmaf(kv, wc[kk * 32], acc[kk]);
    }

#pragma unroll
    for (int kk = 0; kk < NT; ++kk) {
        acc[kk] += __shfl_xor_sync(0xffffffffu, acc[kk], 8);
        acc[kk] += __shfl_xor_sync(0xffffffffu, acc[kk], 16);
        acc[kk] += b2s[kk];
    }

    float m = acc[0];
#pragma unroll
    for (int kk = 1; kk < NT; ++kk) m = fmaxf(m, acc[kk]);
    float s = 0.f;
#pragma unroll
    for (int kk = 0; kk < NT; ++kk) {
        acc[kk] = expf(acc[kk] - m);
        s += acc[kk];
    }
    float inv = 1.f / s;

    float* dst = g_attn + (size_t)b * NT * HW + rem;
    const int k_lo = (slice == 0) ? 0 : (13 + (slice - 1) * 12);
    const int k_hi = (slice == 0) ? 13 : (k_lo + 12);
    for (int kk = k_lo; kk < k_hi; ++kk)
        dst[(size_t)kk * HW] = acc[kk] * inv;
}

// =====================================================================
// Kernel C: weighted local sum over 49 dilated taps -> out
// Grid (56, 4, 2), 224 threads. Thread = 2 channels x 2 px.
// x tiles in HALF (from g_xh parity 0), double-buffered cp.async.
// smem 42.2KB -> ~5 CTAs/SM.
// =====================================================================
#define GNCH 16
#define XS_W (GNCH * 7 * 68)                 // 7616 halfs per buffer
#define AT_ELEMS (49 * 60)
#define GATHER_SMEM (AT_ELEMS * 4 + 2 * XS_W * 2)   // 42224

__global__ void __launch_bounds__(224) gather_kernel(float* __restrict__ out)
{
    extern __shared__ __align__(16) float gsm[];
    float* const at = gsm;                              // [49][60] float
    __half* const xs0 = (__half*)(gsm + AT_ELEMS);      // two half x buffers
    const int h = blockIdx.x, b = blockIdx.y;
    const int chalf = blockIdx.z * 128;
    const int tid = threadIdx.x;
    const uint32_t xs_sb = smem_to_u32(xs0);

    // attn tile (float4 loads)
    for (int t = tid; t < 49 * 14; t += 224) {
        int kk = t / 14, p4 = t - kk * 14;
        *reinterpret_cast<float4*>(&at[kk * 60 + p4 * 4]) =
            *reinterpret_cast<const float4*>(
                g_attn + ((size_t)b * NT + kk) * HW + h * WW + p4 * 4);
    }

    // x chunk issue: 16 ch x 7 rows x 17 x 4-half (8B) chunks
    auto issueX = [&](int ch, int buf) {
        const __half* xpc = g_xh + (size_t)(b * CC + chalf + ch * GNCH) * XPCH
                          + (size_t)h * XPR;
        const uint32_t dstb = xs_sb + (uint32_t)buf * (XS_W * 2);
#pragma unroll
        for (int it = 0; it < 9; ++it) {
            int t = tid + it * 224;
            if (t < GNCH * 7 * 17) {
                int c = t / 119;
                int r = t - c * 119;
                int i = r / 17;
                int qd = r - i * 17;
                CP8(dstb + (uint32_t)((c * 7 + i) * 68 + qd * 4) * 2,
                    (const char*)(xpc + (size_t)c * XPCH + i * (2 * XPR) + qd * 4));
            }
        }
        CP_COMMIT();
    };

    const int pg = tid % 28, cg = tid / 28;   // 28 px-pairs x 8 ch-pairs
    const int p0 = pg * 2;
    const int c0 = cg * 2, c1 = c0 + 1;

    issueX(0, 0);

    for (int ch = 0; ch < 8; ++ch) {
        CP_WAIT0();
        __syncthreads();
        if (ch + 1 < 8) issueX(ch + 1, (ch + 1) & 1);

        const __half* xb = xs0 + (ch & 1) * XS_W;
        u64 a0 = 0ull, a1 = 0ull;
#pragma unroll
        for (int i = 0; i < 7; ++i) {
            const __half* xr0 = xb + (c0 * 7 + i) * 68 + p0;
            const __half* xr1 = xb + (c1 * 7 + i) * 68 + p0;
            const float* ar = &at[(i * 7) * 60 + p0];
#pragma unroll
            for (int j = 0; j < 7; ++j) {
                u64 av = lds64(ar + j * 60);
                float2 f0 = __half22float2(
                    *reinterpret_cast<const __half2*>(xr0 + 2 * j));
                float2 f1 = __half22float2(
                    *reinterpret_cast<const __half2*>(xr1 + 2 * j));
                fma2(a0, av, pack2f(f0));
                fma2(a1, av, pack2f(f1));
            }
        }
        size_t ob = (size_t)(b * CC + chalf + ch * GNCH + c0) * HW + h * WW + p0;
        *reinterpret_cast<float2*>(&out[ob])      = unpack2(a0);
        *reinterpret_cast<float2*>(&out[ob + HW]) = unpack2(a1);
        __syncthreads();
    }
}

// =====================================================================
extern "C" void kernel_launch(void* const* d_in, const int* in_sizes, int n_in,
                              void* d_out, int out_size)
{
    const float* x  = (const float*)d_in[0];
    const float* W1 = (const float*)d_in[1];
    const float* b1 = (const float*)d_in[2];
    const float* W2 = (const float*)d_in[3];
    const float* b2 = (const float*)d_in[4];
    for (int i = 0; i < n_in; ++i) {
        switch (in_sizes[i]) {
            case BB * CC * HW: x  = (const float*)d_in[i]; break;
            case CO * CC * NT: W1 = (const float*)d_in[i]; break;
            case CO:           b1 = (const float*)d_in[i]; break;
            case NT * CO:      W2 = (const float*)d_in[i]; break;
            case NT:           b2 = (const float*)d_in[i]; break;
            default: break;
        }
    }
    float* out = (float*)d_out;

    cudaFuncSetAttribute(conv1_mma, cudaFuncAttributeMaxDynamicSharedMemorySize,
                         CONV1_SMEM);
    cudaFuncSetAttribute(gather_kernel, cudaFuncAttributeMaxDynamicSharedMemorySize,
                         GATHER_SMEM);
    prep_all<<<W1T_BLOCKS + XPH_BLOCKS, 256>>>(W1, x);
    conv1_mma<<<dim3(49, KSPL), 512, CONV1_SMEM>>>();
    conv2_softmax_kernel<<<196, 256>>>(W2, b1, b2);
    gather_kernel<<<dim3(56, 4, 2), 224, GATHER_SMEM>>>(out);
}